// round 6
// baseline (speedup 1.0000x reference)
#include <cuda_runtime.h>
#include <cuda_bf16.h>
#include <math.h>
#include <stdint.h>

#define BNUM 2
#define NSEQ 2048
#define DIMD 256
#define NHEAD 8
#define HD 32
#define FFD 1024
#define ROWS (BNUM*NSEQ)   // 4096

typedef __nv_bfloat16 bf16;

#define QSCALE (0.17677669529663687f * 1.4426950408889634f)
#define LOG2E  1.4426950408889634f

// ---------------- scratch (device globals, no allocation) ----------------
__device__ bf16  g_h  [ROWS*DIMD];
__device__ bf16  g_q  [BNUM*NHEAD*NSEQ*HD];
__device__ bf16  g_k  [BNUM*NHEAD*NSEQ*HD];
__device__ bf16  g_vT [BNUM*NHEAD*HD*NSEQ];   // [b][h][d][n]
__device__ float g_o0 [ROWS*DIMD];            // split-K partial O (unnormalized)
__device__ float g_o1 [ROWS*DIMD];
__device__ float g_l0 [BNUM*NHEAD*NSEQ];      // split-K partial row sums
__device__ float g_l1 [BNUM*NHEAD*NSEQ];
__device__ bf16  g_ao [ROWS*DIMD];
__device__ float g_x1 [ROWS*DIMD];
__device__ bf16  g_h2 [ROWS*DIMD];
__device__ bf16  g_mid[ROWS*FFD];
__device__ uint8_t g_code[(size_t)BNUM*NSEQ*NSEQ];   // 0 = masked, else edge_type+1
__device__ bf16  g_wqkv [3*DIMD*DIMD];
__device__ bf16  g_wproj[DIMD*DIMD];
__device__ bf16  g_wf1  [FFD*DIMD];
__device__ bf16  g_wf2  [DIMD*FFD];

// ---------------- helpers ----------------
__device__ __forceinline__ void cpasync16(void* sdst, const void* gsrc){
    unsigned s = (unsigned)__cvta_generic_to_shared(sdst);
    asm volatile("cp.async.cg.shared.global [%0], [%1], 16;" :: "r"(s), "l"(gsrc));
}
#define CP_COMMIT() asm volatile("cp.async.commit_group;")
template<int N> __device__ __forceinline__ void cp_wait(){
    asm volatile("cp.async.wait_group %0;" :: "n"(N));
}

__device__ __forceinline__ void mma16(float* c,
    uint32_t a0, uint32_t a1, uint32_t a2, uint32_t a3,
    uint32_t b0, uint32_t b1)
{
    asm volatile("mma.sync.aligned.m16n8k16.row.col.f32.bf16.bf16.f32 "
        "{%0,%1,%2,%3}, {%4,%5,%6,%7}, {%8,%9}, {%0,%1,%2,%3};"
        : "+f"(c[0]), "+f"(c[1]), "+f"(c[2]), "+f"(c[3])
        : "r"(a0), "r"(a1), "r"(a2), "r"(a3), "r"(b0), "r"(b1));
}
__device__ __forceinline__ float fexp2(float x){
    float y; asm("ex2.approx.f32 %0, %1;" : "=f"(y) : "f"(x)); return y;
}

// ---------------- fused weight convert (tiled transpose, coalesced) ----------
__global__ void __launch_bounds__(256)
wconv_all(const float* __restrict__ w_qkv, const float* __restrict__ w_proj,
          const float* __restrict__ w_f1,  const float* __restrict__ w_f2)
{
    __shared__ float tile[32][33];
    int id = blockIdx.x;
    const float* W; bf16* Wt; int K, N; bool qs = false;
    if (id < 192)      { W = w_qkv;  Wt = g_wqkv;  K = 256;  N = 768;  qs = true; }
    else if (id < 256) { id -= 192; W = w_proj; Wt = g_wproj; K = 256;  N = 256; }
    else if (id < 512) { id -= 256; W = w_f1;   Wt = g_wf1;   K = 256;  N = 1024; }
    else               { id -= 512; W = w_f2;   Wt = g_wf2;   K = 1024; N = 256; }
    int tn = id % (N / 32), tk = id / (N / 32);
    int tx = threadIdx.x & 31, ty = threadIdx.x >> 5;

    #pragma unroll
    for (int r = 0; r < 4; ++r)
        tile[ty + r * 8][tx] = W[(size_t)(tk * 32 + ty + r * 8) * N + tn * 32 + tx];
    __syncthreads();
    float mul = (qs && tn < 8) ? QSCALE : 1.f;
    #pragma unroll
    for (int r = 0; r < 4; ++r) {
        int n = tn * 32 + ty + r * 8;
        Wt[(size_t)n * K + tk * 32 + tx] = __float2bfloat16(tile[tx][ty + r * 8] * mul);
    }
}

// ---------------- edge code precompute ----------------
__global__ void __launch_bounds__(256)
edge_code_kernel(const int* __restrict__ et, const int* __restrict__ nm,
                 uint8_t* __restrict__ code)
{
    int i = blockIdx.x, b = blockIdx.y;
    int bN = b * NSEQ;
    int nmi = nm[bN + i];
    const int* er = et + (size_t)(bN + i) * NSEQ;
    uint8_t* cr = code + (size_t)(bN + i) * NSEQ;
    for (int j = threadIdx.x * 4; j < NSEQ; j += 1024) {
        int4 e = *(const int4*)(er + j);
        int4 m = *(const int4*)(nm + bN + j);
        uchar4 c;
        c.x = (nmi && m.x && (e.x != 0 || i == j    )) ? (uint8_t)(e.x + 1) : 0;
        c.y = (nmi && m.y && (e.y != 0 || i == j + 1)) ? (uint8_t)(e.y + 1) : 0;
        c.z = (nmi && m.z && (e.z != 0 || i == j + 2)) ? (uint8_t)(e.z + 1) : 0;
        c.w = (nmi && m.w && (e.w != 0 || i == j + 3)) ? (uint8_t)(e.w + 1) : 0;
        *(uchar4*)(cr + j) = c;
    }
}

// ---------------- LayerNorm ----------------
__global__ void ln_kernel(const float* __restrict__ x,
                          const float* __restrict__ g,
                          const float* __restrict__ b,
                          bf16* __restrict__ y)
{
    int row = blockIdx.x;
    int t   = threadIdx.x;
    float v = x[(size_t)row * DIMD + t];

    __shared__ float red[8];
    __shared__ float stat[2];

    float s = v;
    #pragma unroll
    for (int o = 16; o > 0; o >>= 1) s += __shfl_xor_sync(0xffffffffu, s, o);
    if ((t & 31) == 0) red[t >> 5] = s;
    __syncthreads();
    if (t < 32) {
        float r = (t < 8) ? red[t] : 0.f;
        #pragma unroll
        for (int o = 4; o > 0; o >>= 1) r += __shfl_xor_sync(0xffffffffu, r, o);
        if (t == 0) stat[0] = r * (1.0f / DIMD);
    }
    __syncthreads();
    float mu = stat[0];
    float d  = v - mu;

    float s2 = d * d;
    #pragma unroll
    for (int o = 16; o > 0; o >>= 1) s2 += __shfl_xor_sync(0xffffffffu, s2, o);
    if ((t & 31) == 0) red[t >> 5] = s2;
    __syncthreads();
    if (t < 32) {
        float r = (t < 8) ? red[t] : 0.f;
        #pragma unroll
        for (int o = 4; o > 0; o >>= 1) r += __shfl_xor_sync(0xffffffffu, r, o);
        if (t == 0) stat[1] = rsqrtf(r * (1.0f / DIMD) + 1e-5f);
    }
    __syncthreads();
    y[(size_t)row * DIMD + t] = __float2bfloat16(d * stat[1] * g[t] + b[t]);
}

// ---------------- split-K merge + normalize -> bf16 ----------------
__global__ void __launch_bounds__(256)
attn_norm_kernel(bf16* __restrict__ outb)
{
    int idx = (blockIdx.x * 256 + threadIdx.x) * 4;   // over ROWS*DIMD
    int row = idx >> 8;                               // 0..4095
    int dimpos = idx & 255;
    int h = dimpos >> 5;
    int b = row >> 11, n = row & 2047;
    int li = (b * NHEAD + h) * NSEQ + n;
    float l = g_l0[li] + g_l1[li];
    float inv = l > 0.f ? 1.f / l : 0.f;
    float4 o0 = *(const float4*)&g_o0[idx];
    float4 o1 = *(const float4*)&g_o1[idx];
    __nv_bfloat162 r0 = __floats2bfloat162_rn((o0.x + o1.x) * inv, (o0.y + o1.y) * inv);
    __nv_bfloat162 r1 = __floats2bfloat162_rn((o0.z + o1.z) * inv, (o0.w + o1.w) * inv);
    uint2 pk = make_uint2(*(uint32_t*)&r0, *(uint32_t*)&r1);
    *(uint2*)&outb[idx] = pk;
}

// ---------------- bf16 MMA GEMM, 3-stage cp.async pipeline ----------------
template<int BM, int BN, int KD, int NT, int MODE>
__global__ void __launch_bounds__(256, 2)
mma_gemm(const bf16* __restrict__ A, const bf16* __restrict__ Wt,
         const float* __restrict__ bias, const float* __restrict__ extra,
         const int* __restrict__ nm, float* __restrict__ outf, bf16* __restrict__ outb)
{
    constexpr int WM  = BM / 32;
    constexpr int WN  = 8 / WM;
    constexpr int WTN = BN / WN;
    constexpr int NTN = WTN / 8;
    constexpr int CA  = (BM * 32 / 8) / 256;
    constexpr int CB  = (BN * 32 / 8) / 256;
    constexpr int NK  = KD / 32;

    extern __shared__ __align__(16) bf16 gsm[];
    bf16* As = gsm;                 // [3][BM*40]
    bf16* Bs = gsm + 3 * BM * 40;   // [3][BN*40]

    int t = threadIdx.x, lane = t & 31, warp = t >> 5;
    int gid = lane >> 2, tig = lane & 3;
    int wm = warp % WM, wn = warp / WM;
    int rm = blockIdx.y * BM, cn = blockIdx.x * BN;
    const bf16* Ag = A  + (size_t)rm * KD;
    const bf16* Bg = Wt + (size_t)cn * KD;

    float acc[2][NTN][4];
    #pragma unroll
    for (int mi = 0; mi < 2; ++mi)
        #pragma unroll
        for (int nt = 0; nt < NTN; ++nt)
            #pragma unroll
            for (int q = 0; q < 4; ++q) acc[mi][nt][q] = 0.f;

    auto load_stage = [&](int k0, int st) {
        bf16* Asd = As + st * BM * 40;
        bf16* Bsd = Bs + st * BN * 40;
        #pragma unroll
        for (int i = 0; i < CA; ++i) {
            int c = t + i * 256, row = c >> 2, off = (c & 3) * 8;
            cpasync16(&Asd[row * 40 + off], Ag + (size_t)row * KD + k0 + off);
        }
        #pragma unroll
        for (int i = 0; i < CB; ++i) {
            int c = t + i * 256, row = c >> 2, off = (c & 3) * 8;
            cpasync16(&Bsd[row * 40 + off], Bg + (size_t)row * KD + k0 + off);
        }
        CP_COMMIT();
    };

    load_stage(0, 0);
    load_stage(32, 1);
    for (int i = 0; i < NK; ++i) {
        int st = i % 3;
        if (i + 1 < NK) cp_wait<1>(); else cp_wait<0>();
        __syncthreads();
        if (i + 2 < NK) load_stage((i + 2) * 32, (i + 2) % 3);

        const uint32_t* A32 = (const uint32_t*)(As + st * BM * 40);
        const uint32_t* B32 = (const uint32_t*)(Bs + st * BN * 40);
        #pragma unroll
        for (int ks = 0; ks < 2; ++ks) {
            uint32_t af[2][4];
            #pragma unroll
            for (int mi = 0; mi < 2; ++mi) {
                int base = wm * 32 + mi * 16;
                af[mi][0] = A32[(base + gid    ) * 20 + ks * 8 + tig    ];
                af[mi][1] = A32[(base + gid + 8) * 20 + ks * 8 + tig    ];
                af[mi][2] = A32[(base + gid    ) * 20 + ks * 8 + tig + 4];
                af[mi][3] = A32[(base + gid + 8) * 20 + ks * 8 + tig + 4];
            }
            #pragma unroll
            for (int nt = 0; nt < NTN; ++nt) {
                int n = wn * WTN + nt * 8 + gid;
                uint32_t b0 = B32[n * 20 + ks * 8 + tig];
                uint32_t b1 = B32[n * 20 + ks * 8 + tig + 4];
                mma16(acc[0][nt], af[0][0], af[0][1], af[0][2], af[0][3], b0, b1);
                mma16(acc[1][nt], af[1][0], af[1][1], af[1][2], af[1][3], b0, b1);
            }
        }
    }
    __syncthreads();

    // ---- epilogue ----
    #pragma unroll
    for (int mi = 0; mi < 2; ++mi) {
        #pragma unroll
        for (int half = 0; half < 2; ++half) {
            int r = rm + wm * 32 + mi * 16 + gid + half * 8;
            float mrow = 0.f;
            if (MODE == 1 || MODE == 3) mrow = nm[r] ? 1.f : 0.f;
            #pragma unroll
            for (int nt = 0; nt < NTN; ++nt) {
                int c = cn + wn * WTN + nt * 8 + tig * 2;
                float bmul = (MODE == 0 && c < DIMD) ? QSCALE : 1.f;
                float v0 = acc[mi][nt][half * 2 + 0] + bias[c] * bmul;
                float v1 = acc[mi][nt][half * 2 + 1] + bias[c + 1] * bmul;
                if (MODE == 0) {
                    int part = c >> 8, hh = (c >> 5) & 7, dd = c & 31;
                    int b2 = r >> 11, n = r & 2047;
                    if (part == 2) {
                        size_t base = ((size_t)(b2 * NHEAD + hh) * HD + dd) * NSEQ + n;
                        g_vT[base]        = __float2bfloat16(v0);
                        g_vT[base + NSEQ] = __float2bfloat16(v1);
                    } else {
                        bf16* dst = (part == 0) ? g_q : g_k;
                        __nv_bfloat162 pv = __floats2bfloat162_rn(v0, v1);
                        *(__nv_bfloat162*)&dst[((size_t)(b2 * NHEAD + hh) * NSEQ + n) * HD + dd] = pv;
                    }
                } else if (MODE == 2) {
                    float g0 = 0.5f * v0 * (1.f + erff(v0 * 0.70710678118654752f));
                    float g1 = 0.5f * v1 * (1.f + erff(v1 * 0.70710678118654752f));
                    *(__nv_bfloat162*)&outb[(size_t)r * NT + c] = __floats2bfloat162_rn(g0, g1);
                } else {
                    float2 ex = *(const float2*)&extra[(size_t)r * NT + c];
                    *(float2*)&outf[(size_t)r * NT + c] =
                        make_float2(ex.x + v0 * mrow, ex.y + v1 * mrow);
                }
            }
        }
    }
}

// ---------------- bf16 MMA flash attention, split-K x2, register P ----------------
// grid 512: bid = ((b*2 + s)*16 + rb)*8 + h.  Block does key tiles [s*8, s*8+8).
__global__ void __launch_bounds__(256, 2)
attn_mma(const float* __restrict__ ebt)
{
    extern __shared__ __align__(16) bf16 smb[];
    bf16* Qs  = smb;             // 128*40
    bf16* Ks0 = Qs  + 5120;      // 3 stages x 128*40
    bf16* Vs0 = Ks0 + 3 * 5120;  // 3 stages x 32*136
    float* tbl2 = (float*)(Vs0 + 3 * 4352);  // 16

    int tid = threadIdx.x, lane = tid & 31, warp = tid >> 5;
    int gid = lane >> 2, tig = lane & 3;
    int bid = blockIdx.x;
    int h = bid & 7, rb = (bid >> 3) & 15, s = (bid >> 7) & 1, b = bid >> 8;
    int r0 = rb * 128;
    int lo = s * 8, hi = lo + 8;
    const int bN = b * NSEQ;
    int w16 = warp * 16;

    const bf16* qptr = g_q  + ((size_t)(b * NHEAD + h) * NSEQ + r0) * HD;
    const bf16* kbh  = g_k  + (size_t)(b * NHEAD + h) * NSEQ * HD;
    const bf16* vT   = g_vT + (size_t)(b * NHEAD + h) * HD * NSEQ;

    auto load_kv = [&](int kt, int st) {
        int j0 = kt * 128;
        bf16* Ksd = Ks0 + st * 5120;
        bf16* Vsd = Vs0 + st * 4352;
        #pragma unroll
        for (int i = 0; i < 2; ++i) {
            int c = tid + i * 256, row = c >> 2, off = (c & 3) * 8;
            cpasync16(&Ksd[row * 40 + off], kbh + (size_t)(j0 + row) * HD + off);
        }
        #pragma unroll
        for (int i = 0; i < 2; ++i) {
            int c = tid + i * 256, d = c >> 4, off = (c & 15) * 8;
            cpasync16(&Vsd[d * 136 + off], vT + (size_t)d * NSEQ + j0 + off);
        }
        CP_COMMIT();
    };

    load_kv(lo, 0);
    load_kv(lo + 1, 1);

    #pragma unroll
    for (int i = 0; i < 2; ++i) {
        int c = tid + i * 256, row = c >> 2, off = (c & 3) * 8;
        *(uint4*)&Qs[row * 40 + off] = *(const uint4*)(qptr + (size_t)row * HD + off);
    }
    if (tid < 16)
        tbl2[tid] = (tid == 0) ? -30000.f
                  : (tid < 10 ? ebt[(tid - 1) * NHEAD + h] * LOG2E : 0.f);
    __syncthreads();

    // Q fragments for this warp's 16 rows
    const uint32_t* Q32 = (const uint32_t*)Qs;
    uint32_t qa[2][4];
    #pragma unroll
    for (int ks = 0; ks < 2; ++ks) {
        qa[ks][0] = Q32[(w16 + gid    ) * 20 + ks * 8 + tig    ];
        qa[ks][1] = Q32[(w16 + gid + 8) * 20 + ks * 8 + tig    ];
        qa[ks][2] = Q32[(w16 + gid    ) * 20 + ks * 8 + tig + 4];
        qa[ks][3] = Q32[(w16 + gid + 8) * 20 + ks * 8 + tig + 4];
    }

    float oacc[4][4];
    #pragma unroll
    for (int nt = 0; nt < 4; ++nt)
        #pragma unroll
        for (int q = 0; q < 4; ++q) oacc[nt][q] = 0.f;
    float lp0 = 0.f, lp1 = 0.f;

    const uint8_t* crow0 = g_code + (size_t)(bN + r0 + w16 + gid    ) * NSEQ;
    const uint8_t* crow1 = g_code + (size_t)(bN + r0 + w16 + gid + 8) * NSEQ;

    for (int kt = lo; kt < hi; ++kt) {
        int st = (kt - lo) % 3, j0 = kt * 128;
        if (kt + 1 < hi) cp_wait<1>(); else cp_wait<0>();
        __syncthreads();
        if (kt + 2 < hi) load_kv(kt + 2, (kt - lo + 2) % 3);

        // ---- QK^T: warp computes its 16 rows x full 128 cols ----
        const uint32_t* K32 = (const uint32_t*)(Ks0 + st * 5120);
        float sacc[16][4];
        #pragma unroll
        for (int nt = 0; nt < 16; ++nt)
            #pragma unroll
            for (int q = 0; q < 4; ++q) sacc[nt][q] = 0.f;
        #pragma unroll
        for (int ks = 0; ks < 2; ++ks) {
            #pragma unroll
            for (int nt = 0; nt < 16; ++nt) {
                int n = nt * 8 + gid;
                uint32_t b0 = K32[n * 20 + ks * 8 + tig];
                uint32_t b1 = K32[n * 20 + ks * 8 + tig + 4];
                mma16(sacc[nt], qa[ks][0], qa[ks][1], qa[ks][2], qa[ks][3], b0, b1);
            }
        }

        // ---- exp epilogue in registers: C-frag -> PV A-frag ----
        uint32_t pfrag[16][2];
        #pragma unroll
        for (int nt = 0; nt < 16; ++nt) {
            int coff = j0 + nt * 8 + tig * 2;
            unsigned short c0 = *(const unsigned short*)(crow0 + coff);
            unsigned short c1 = *(const unsigned short*)(crow1 + coff);
            float p00 = fexp2(sacc[nt][0] + tbl2[c0 & 0xff]);
            float p01 = fexp2(sacc[nt][1] + tbl2[c0 >> 8]);
            float p10 = fexp2(sacc[nt][2] + tbl2[c1 & 0xff]);
            float p11 = fexp2(sacc[nt][3] + tbl2[c1 >> 8]);
            lp0 += p00 + p01;
            lp1 += p10 + p11;
            __nv_bfloat162 a = __floats2bfloat162_rn(p00, p01);
            __nv_bfloat162 c = __floats2bfloat162_rn(p10, p11);
            pfrag[nt][0] = *(uint32_t*)&a;
            pfrag[nt][1] = *(uint32_t*)&c;
        }

        // ---- PV: O[16x32] += P[16x128] V[128x32] ----
        const uint32_t* V32 = (const uint32_t*)(Vs0 + st * 4352);
        #pragma unroll
        for (int ks2 = 0; ks2 < 8; ++ks2) {
            uint32_t a0 = pfrag[2 * ks2    ][0];
            uint32_t a1 = pfrag[2 * ks2    ][1];
            uint32_t a2 = pfrag[2 * ks2 + 1][0];
            uint32_t a3 = pfrag[2 * ks2 + 1][1];
            #pragma unroll
            for (int nt2 = 0; nt2 < 4; ++nt2) {
                int d = nt2 * 8 + gid;
                uint32_t b0 = V32[d * 68 + ks2 * 8 + tig];
                uint32_t b1 = V32[d * 68 + ks2 * 8 + tig + 4];
                mma16(oacc[nt2], a0, a1, a2, a3, b0, b1);
            }
        }
    }

    // ---- partial row sums (quad butterfly) + partial O stores ----
    lp0 += __shfl_xor_sync(0xffffffffu, lp0, 1);
    lp0 += __shfl_xor_sync(0xffffffffu, lp0, 2);
    lp1 += __shfl_xor_sync(0xffffffffu, lp1, 1);
    lp1 += __shfl_xor_sync(0xffffffffu, lp1, 2);

    float* po = s ? g_o1 : g_o0;
    float* pl = s ? g_l1 : g_l0;
    if (tig == 0) {
        int li = (b * NHEAD + h) * NSEQ + r0 + w16 + gid;
        pl[li]     = lp0;
        pl[li + 8] = lp1;
    }
    float* od = po + ((size_t)(bN + r0)) * DIMD + h * HD;
    #pragma unroll
    for (int nt = 0; nt < 4; ++nt) {
        int d = nt * 8 + tig * 2;
        *(float2*)&od[(size_t)(w16 + gid    ) * DIMD + d] = make_float2(oacc[nt][0], oacc[nt][1]);
        *(float2*)&od[(size_t)(w16 + gid + 8) * DIMD + d] = make_float2(oacc[nt][2], oacc[nt][3]);
    }
}

// ---------------- launch ----------------
static void* sym_addr(const void* sym)
{
    void* p = nullptr;
    cudaGetSymbolAddress(&p, sym);
    return p;
}

extern "C" void kernel_launch(void* const* d_in, const int* in_sizes, int n_in,
                              void* d_out, int out_size)
{
    const float* x      = (const float*)d_in[0];
    const int*   etyp   = (const int*)  d_in[1];
    const int*   nmask  = (const int*)  d_in[2];
    const float* qkv_w  = (const float*)d_in[3];
    const float* qkv_b  = (const float*)d_in[4];
    const float* proj_w = (const float*)d_in[5];
    const float* proj_b = (const float*)d_in[6];
    const float* ebt    = (const float*)d_in[7];
    const float* ln1_g  = (const float*)d_in[8];
    const float* ln1_b  = (const float*)d_in[9];
    const float* ln2_g  = (const float*)d_in[10];
    const float* ln2_b  = (const float*)d_in[11];
    const float* ffn_w1 = (const float*)d_in[12];
    const float* ffn_b1 = (const float*)d_in[13];
    const float* ffn_w2 = (const float*)d_in[14];
    const float* ffn_b2 = (const float*)d_in[15];
    float* out = (float*)d_out;

    bf16*  ph    = (bf16*) sym_addr(g_h);
    bf16*  pao   = (bf16*) sym_addr(g_ao);
    float* px1   = (float*)sym_addr(g_x1);
    bf16*  ph2   = (bf16*) sym_addr(g_h2);
    bf16*  pmid  = (bf16*) sym_addr(g_mid);
    bf16*  pwqkv = (bf16*) sym_addr(g_wqkv);
    bf16*  pwproj= (bf16*) sym_addr(g_wproj);
    bf16*  pwf1  = (bf16*) sym_addr(g_wf1);
    bf16*  pwf2  = (bf16*) sym_addr(g_wf2);
    uint8_t* pcode = (uint8_t*)sym_addr(g_code);

    const int ATTN_SMEM = (5120 + 3 * 5120 + 3 * 4352) * 2 + 64;  // 67136
    const int GSM_64_128 = 3 * (64 * 40 + 128 * 40) * 2;          // 46080
    const int GSM_64_64  = 3 * (64 * 40 + 64 * 40) * 2;           // 30720
    cudaFuncSetAttribute(attn_mma, cudaFuncAttributeMaxDynamicSharedMemorySize, ATTN_SMEM);
    cudaFuncSetAttribute(mma_gemm<64,128,DIMD,3*DIMD,0>, cudaFuncAttributeMaxDynamicSharedMemorySize, GSM_64_128);
    cudaFuncSetAttribute(mma_gemm<64,64,DIMD,DIMD,1>,    cudaFuncAttributeMaxDynamicSharedMemorySize, GSM_64_64);
    cudaFuncSetAttribute(mma_gemm<64,128,DIMD,FFD,2>,    cudaFuncAttributeMaxDynamicSharedMemorySize, GSM_64_128);
    cudaFuncSetAttribute(mma_gemm<64,64,FFD,DIMD,3>,     cudaFuncAttributeMaxDynamicSharedMemorySize, GSM_64_64);

    // 0) fused weight conversion + edge code precompute
    wconv_all<<<768, 256>>>(qkv_w, proj_w, ffn_w1, ffn_w2);
    edge_code_kernel<<<dim3(NSEQ, BNUM), 256>>>(etyp, nmask, pcode);

    // 1) LN1 -> bf16
    ln_kernel<<<ROWS, 256>>>(x, ln1_g, ln1_b, ph);
    // 2) QKV GEMM + scatter (q scaled; k normal; v transposed)
    mma_gemm<64, 128, DIMD, 3*DIMD, 0><<<dim3(6, 64), 256, GSM_64_128>>>(
        ph, pwqkv, qkv_b, nullptr, nullptr, nullptr, nullptr);
    // 3) attention (split-K x2, partial buffers)
    attn_mma<<<BNUM * 2 * NHEAD * (NSEQ / 128), 256, ATTN_SMEM>>>(ebt);
    // 3b) merge + normalize -> bf16 g_ao
    attn_norm_kernel<<<ROWS * DIMD / 1024, 256>>>(pao);
    // 4) proj + residual + node mask -> x1 (fp32)
    mma_gemm<64, 64, DIMD, DIMD, 1><<<dim3(4, 64), 256, GSM_64_64>>>(
        pao, pwproj, proj_b, x, nmask, px1, nullptr);
    // 5) LN2 -> bf16
    ln_kernel<<<ROWS, 256>>>(px1, ln2_g, ln2_b, ph2);
    // 6) FFN1 + exact GELU -> bf16 mid
    mma_gemm<64, 128, DIMD, FFD, 2><<<dim3(8, 64), 256, GSM_64_128>>>(
        ph2, pwf1, ffn_b1, nullptr, nullptr, nullptr, pmid);
    // 7) FFN2 + node mask + residual -> out (fp32)
    mma_gemm<64, 64, FFD, DIMD, 3><<<dim3(4, 64), 256, GSM_64_64>>>(
        pmid, pwf2, ffn_b2, px1, nmask, out, nullptr);
}

// round 7
// speedup vs baseline: 1.0702x; 1.0702x over previous
#include <cuda_runtime.h>
#include <cuda_bf16.h>
#include <math.h>
#include <stdint.h>

#define BNUM 2
#define NSEQ 2048
#define DIMD 256
#define NHEAD 8
#define HD 32
#define FFD 1024
#define ROWS (BNUM*NSEQ)   // 4096

typedef __nv_bfloat16 bf16;

#define QSCALE (0.17677669529663687f * 1.4426950408889634f)
#define LOG2E  1.4426950408889634f

// ---------------- scratch (device globals, no allocation) ----------------
__device__ bf16  g_h  [ROWS*DIMD];
__device__ bf16  g_q  [BNUM*NHEAD*NSEQ*HD];
__device__ bf16  g_k  [BNUM*NHEAD*NSEQ*HD];
__device__ bf16  g_vT [BNUM*NHEAD*HD*NSEQ];   // [b][h][d][n]
__device__ bf16  g_ao [ROWS*DIMD];
__device__ float g_x1 [ROWS*DIMD];
__device__ bf16  g_h2 [ROWS*DIMD];
__device__ bf16  g_mid[ROWS*FFD];
__device__ uint8_t g_code[(size_t)BNUM*NSEQ*NSEQ];   // 0 = masked, else edge_type+1
__device__ bf16  g_wqkv [3*DIMD*DIMD];
__device__ bf16  g_wproj[DIMD*DIMD];
__device__ bf16  g_wf1  [FFD*DIMD];
__device__ bf16  g_wf2  [DIMD*FFD];

// ---------------- helpers ----------------
__device__ __forceinline__ void cpasync16(void* sdst, const void* gsrc){
    unsigned s = (unsigned)__cvta_generic_to_shared(sdst);
    asm volatile("cp.async.cg.shared.global [%0], [%1], 16;" :: "r"(s), "l"(gsrc));
}
#define CP_COMMIT() asm volatile("cp.async.commit_group;")
template<int N> __device__ __forceinline__ void cp_wait(){
    asm volatile("cp.async.wait_group %0;" :: "n"(N));
}

__device__ __forceinline__ void mma16(float* c,
    uint32_t a0, uint32_t a1, uint32_t a2, uint32_t a3,
    uint32_t b0, uint32_t b1)
{
    asm volatile("mma.sync.aligned.m16n8k16.row.col.f32.bf16.bf16.f32 "
        "{%0,%1,%2,%3}, {%4,%5,%6,%7}, {%8,%9}, {%0,%1,%2,%3};"
        : "+f"(c[0]), "+f"(c[1]), "+f"(c[2]), "+f"(c[3])
        : "r"(a0), "r"(a1), "r"(a2), "r"(a3), "r"(b0), "r"(b1));
}
__device__ __forceinline__ float fexp2(float x){
    float y; asm("ex2.approx.f32 %0, %1;" : "=f"(y) : "f"(x)); return y;
}

// ---------------- fused weight convert (tiled transpose, coalesced) ----------
__global__ void __launch_bounds__(256)
wconv_all(const float* __restrict__ w_qkv, const float* __restrict__ w_proj,
          const float* __restrict__ w_f1,  const float* __restrict__ w_f2)
{
    __shared__ float tile[32][33];
    int id = blockIdx.x;
    const float* W; bf16* Wt; int K, N; bool qs = false;
    if (id < 192)      { W = w_qkv;  Wt = g_wqkv;  K = 256;  N = 768;  qs = true; }
    else if (id < 256) { id -= 192; W = w_proj; Wt = g_wproj; K = 256;  N = 256; }
    else if (id < 512) { id -= 256; W = w_f1;   Wt = g_wf1;   K = 256;  N = 1024; }
    else               { id -= 512; W = w_f2;   Wt = g_wf2;   K = 1024; N = 256; }
    int tn = id % (N / 32), tk = id / (N / 32);
    int tx = threadIdx.x & 31, ty = threadIdx.x >> 5;

    #pragma unroll
    for (int r = 0; r < 4; ++r)
        tile[ty + r * 8][tx] = W[(size_t)(tk * 32 + ty + r * 8) * N + tn * 32 + tx];
    __syncthreads();
    float mul = (qs && tn < 8) ? QSCALE : 1.f;
    #pragma unroll
    for (int r = 0; r < 4; ++r) {
        int n = tn * 32 + ty + r * 8;
        Wt[(size_t)n * K + tk * 32 + tx] = __float2bfloat16(tile[tx][ty + r * 8] * mul);
    }
}

// ---------------- edge code precompute ----------------
__global__ void __launch_bounds__(256)
edge_code_kernel(const int* __restrict__ et, const int* __restrict__ nm,
                 uint8_t* __restrict__ code)
{
    int i = blockIdx.x, b = blockIdx.y;
    int bN = b * NSEQ;
    int nmi = nm[bN + i];
    const int* er = et + (size_t)(bN + i) * NSEQ;
    uint8_t* cr = code + (size_t)(bN + i) * NSEQ;
    for (int j = threadIdx.x * 4; j < NSEQ; j += 1024) {
        int4 e = *(const int4*)(er + j);
        int4 m = *(const int4*)(nm + bN + j);
        uchar4 c;
        c.x = (nmi && m.x && (e.x != 0 || i == j    )) ? (uint8_t)(e.x + 1) : 0;
        c.y = (nmi && m.y && (e.y != 0 || i == j + 1)) ? (uint8_t)(e.y + 1) : 0;
        c.z = (nmi && m.z && (e.z != 0 || i == j + 2)) ? (uint8_t)(e.z + 1) : 0;
        c.w = (nmi && m.w && (e.w != 0 || i == j + 3)) ? (uint8_t)(e.w + 1) : 0;
        *(uchar4*)(cr + j) = c;
    }
}

// ---------------- LayerNorm ----------------
__global__ void ln_kernel(const float* __restrict__ x,
                          const float* __restrict__ g,
                          const float* __restrict__ b,
                          bf16* __restrict__ y)
{
    int row = blockIdx.x;
    int t   = threadIdx.x;
    float v = x[(size_t)row * DIMD + t];

    __shared__ float red[8];
    __shared__ float stat[2];

    float s = v;
    #pragma unroll
    for (int o = 16; o > 0; o >>= 1) s += __shfl_xor_sync(0xffffffffu, s, o);
    if ((t & 31) == 0) red[t >> 5] = s;
    __syncthreads();
    if (t < 32) {
        float r = (t < 8) ? red[t] : 0.f;
        #pragma unroll
        for (int o = 4; o > 0; o >>= 1) r += __shfl_xor_sync(0xffffffffu, r, o);
        if (t == 0) stat[0] = r * (1.0f / DIMD);
    }
    __syncthreads();
    float mu = stat[0];
    float d  = v - mu;

    float s2 = d * d;
    #pragma unroll
    for (int o = 16; o > 0; o >>= 1) s2 += __shfl_xor_sync(0xffffffffu, s2, o);
    if ((t & 31) == 0) red[t >> 5] = s2;
    __syncthreads();
    if (t < 32) {
        float r = (t < 8) ? red[t] : 0.f;
        #pragma unroll
        for (int o = 4; o > 0; o >>= 1) r += __shfl_xor_sync(0xffffffffu, r, o);
        if (t == 0) stat[1] = rsqrtf(r * (1.0f / DIMD) + 1e-5f);
    }
    __syncthreads();
    y[(size_t)row * DIMD + t] = __float2bfloat16(d * stat[1] * g[t] + b[t]);
}

// ---------------- bf16 MMA GEMM, 3-stage cp.async pipeline ----------------
template<int BM, int BN, int KD, int NT, int MODE>
__global__ void __launch_bounds__(256, 2)
mma_gemm(const bf16* __restrict__ A, const bf16* __restrict__ Wt,
         const float* __restrict__ bias, const float* __restrict__ extra,
         const int* __restrict__ nm, float* __restrict__ outf, bf16* __restrict__ outb)
{
    constexpr int WM  = BM / 32;
    constexpr int WN  = 8 / WM;
    constexpr int WTN = BN / WN;
    constexpr int NTN = WTN / 8;
    constexpr int CA  = (BM * 32 / 8) / 256;
    constexpr int CB  = (BN * 32 / 8) / 256;
    constexpr int NK  = KD / 32;

    extern __shared__ __align__(16) bf16 gsm[];
    bf16* As = gsm;                 // [3][BM*40]
    bf16* Bs = gsm + 3 * BM * 40;   // [3][BN*40]

    int t = threadIdx.x, lane = t & 31, warp = t >> 5;
    int gid = lane >> 2, tig = lane & 3;
    int wm = warp % WM, wn = warp / WM;
    int rm = blockIdx.y * BM, cn = blockIdx.x * BN;
    const bf16* Ag = A  + (size_t)rm * KD;
    const bf16* Bg = Wt + (size_t)cn * KD;

    float acc[2][NTN][4];
    #pragma unroll
    for (int mi = 0; mi < 2; ++mi)
        #pragma unroll
        for (int nt = 0; nt < NTN; ++nt)
            #pragma unroll
            for (int q = 0; q < 4; ++q) acc[mi][nt][q] = 0.f;

    auto load_stage = [&](int k0, int st) {
        bf16* Asd = As + st * BM * 40;
        bf16* Bsd = Bs + st * BN * 40;
        #pragma unroll
        for (int i = 0; i < CA; ++i) {
            int c = t + i * 256, row = c >> 2, off = (c & 3) * 8;
            cpasync16(&Asd[row * 40 + off], Ag + (size_t)row * KD + k0 + off);
        }
        #pragma unroll
        for (int i = 0; i < CB; ++i) {
            int c = t + i * 256, row = c >> 2, off = (c & 3) * 8;
            cpasync16(&Bsd[row * 40 + off], Bg + (size_t)row * KD + k0 + off);
        }
        CP_COMMIT();
    };

    load_stage(0, 0);
    load_stage(32, 1);
    for (int i = 0; i < NK; ++i) {
        int st = i % 3;
        if (i + 1 < NK) cp_wait<1>(); else cp_wait<0>();
        __syncthreads();
        if (i + 2 < NK) load_stage((i + 2) * 32, (i + 2) % 3);

        const uint32_t* A32 = (const uint32_t*)(As + st * BM * 40);
        const uint32_t* B32 = (const uint32_t*)(Bs + st * BN * 40);
        #pragma unroll
        for (int ks = 0; ks < 2; ++ks) {
            uint32_t af[2][4];
            #pragma unroll
            for (int mi = 0; mi < 2; ++mi) {
                int base = wm * 32 + mi * 16;
                af[mi][0] = A32[(base + gid    ) * 20 + ks * 8 + tig    ];
                af[mi][1] = A32[(base + gid + 8) * 20 + ks * 8 + tig    ];
                af[mi][2] = A32[(base + gid    ) * 20 + ks * 8 + tig + 4];
                af[mi][3] = A32[(base + gid + 8) * 20 + ks * 8 + tig + 4];
            }
            #pragma unroll
            for (int nt = 0; nt < NTN; ++nt) {
                int n = wn * WTN + nt * 8 + gid;
                uint32_t b0 = B32[n * 20 + ks * 8 + tig];
                uint32_t b1 = B32[n * 20 + ks * 8 + tig + 4];
                mma16(acc[0][nt], af[0][0], af[0][1], af[0][2], af[0][3], b0, b1);
                mma16(acc[1][nt], af[1][0], af[1][1], af[1][2], af[1][3], b0, b1);
            }
        }
    }
    __syncthreads();

    // ---- epilogue ----
    #pragma unroll
    for (int mi = 0; mi < 2; ++mi) {
        #pragma unroll
        for (int half = 0; half < 2; ++half) {
            int r = rm + wm * 32 + mi * 16 + gid + half * 8;
            float mrow = 0.f;
            if (MODE == 1 || MODE == 3) mrow = nm[r] ? 1.f : 0.f;
            #pragma unroll
            for (int nt = 0; nt < NTN; ++nt) {
                int c = cn + wn * WTN + nt * 8 + tig * 2;
                float bmul = (MODE == 0 && c < DIMD) ? QSCALE : 1.f;
                float v0 = acc[mi][nt][half * 2 + 0] + bias[c] * bmul;
                float v1 = acc[mi][nt][half * 2 + 1] + bias[c + 1] * bmul;
                if (MODE == 0) {
                    int part = c >> 8, hh = (c >> 5) & 7, dd = c & 31;
                    int b2 = r >> 11, n = r & 2047;
                    if (part == 2) {
                        size_t base = ((size_t)(b2 * NHEAD + hh) * HD + dd) * NSEQ + n;
                        g_vT[base]        = __float2bfloat16(v0);
                        g_vT[base + NSEQ] = __float2bfloat16(v1);
                    } else {
                        bf16* dst = (part == 0) ? g_q : g_k;
                        __nv_bfloat162 pv = __floats2bfloat162_rn(v0, v1);
                        *(__nv_bfloat162*)&dst[((size_t)(b2 * NHEAD + hh) * NSEQ + n) * HD + dd] = pv;
                    }
                } else if (MODE == 2) {
                    float g0 = 0.5f * v0 * (1.f + erff(v0 * 0.70710678118654752f));
                    float g1 = 0.5f * v1 * (1.f + erff(v1 * 0.70710678118654752f));
                    *(__nv_bfloat162*)&outb[(size_t)r * NT + c] = __floats2bfloat162_rn(g0, g1);
                } else {
                    float2 ex = *(const float2*)&extra[(size_t)r * NT + c];
                    *(float2*)&outf[(size_t)r * NT + c] =
                        make_float2(ex.x + v0 * mrow, ex.y + v1 * mrow);
                }
            }
        }
    }
}

// ---------------- bf16 MMA flash attention ----------------
// 8 warps; warp w owns rows w*16..+15 for QK and PV (C-frag == A-frag).
// Edge codes prefetched to registers; exp interleaved with PV MMAs.
__global__ void __launch_bounds__(256, 2)
attn_mma(const float* __restrict__ ebt)
{
    extern __shared__ __align__(16) bf16 smb[];
    bf16* Qs  = smb;             // 128*40
    bf16* Ks0 = Qs  + 5120;      // 3 stages x 128*40
    bf16* Vs0 = Ks0 + 3 * 5120;  // 3 stages x 32*136
    float* tbl2 = (float*)(Vs0 + 3 * 4352);  // 16

    int tid = threadIdx.x, lane = tid & 31, warp = tid >> 5;
    int gid = lane >> 2, tig = lane & 3;
    int bid = blockIdx.x;
    int h = bid & 7, rb = (bid >> 3) & 15, b = bid >> 7;  // h fastest: code L2 reuse
    int r0 = rb * 128;
    const int bN = b * NSEQ;
    int w16 = warp * 16;

    const bf16* qptr = g_q  + ((size_t)(b * NHEAD + h) * NSEQ + r0) * HD;
    const bf16* kbh  = g_k  + (size_t)(b * NHEAD + h) * NSEQ * HD;
    const bf16* vT   = g_vT + (size_t)(b * NHEAD + h) * HD * NSEQ;

    auto load_kv = [&](int kt, int st) {
        int j0 = kt * 128;
        bf16* Ksd = Ks0 + st * 5120;
        bf16* Vsd = Vs0 + st * 4352;
        #pragma unroll
        for (int i = 0; i < 2; ++i) {
            int c = tid + i * 256, row = c >> 2, off = (c & 3) * 8;
            cpasync16(&Ksd[row * 40 + off], kbh + (size_t)(j0 + row) * HD + off);
        }
        #pragma unroll
        for (int i = 0; i < 2; ++i) {
            int c = tid + i * 256, d = c >> 4, off = (c & 15) * 8;
            cpasync16(&Vsd[d * 136 + off], vT + (size_t)d * NSEQ + j0 + off);
        }
        CP_COMMIT();
    };

    load_kv(0, 0);
    load_kv(1, 1);

    #pragma unroll
    for (int i = 0; i < 2; ++i) {
        int c = tid + i * 256, row = c >> 2, off = (c & 3) * 8;
        *(uint4*)&Qs[row * 40 + off] = *(const uint4*)(qptr + (size_t)row * HD + off);
    }
    if (tid < 16)
        tbl2[tid] = (tid == 0) ? -30000.f
                  : (tid < 10 ? ebt[(tid - 1) * NHEAD + h] * LOG2E : 0.f);
    __syncthreads();

    // Q fragments for this warp's 16 rows
    const uint32_t* Q32 = (const uint32_t*)Qs;
    uint32_t qa[2][4];
    #pragma unroll
    for (int ks = 0; ks < 2; ++ks) {
        qa[ks][0] = Q32[(w16 + gid    ) * 20 + ks * 8 + tig    ];
        qa[ks][1] = Q32[(w16 + gid + 8) * 20 + ks * 8 + tig    ];
        qa[ks][2] = Q32[(w16 + gid    ) * 20 + ks * 8 + tig + 4];
        qa[ks][3] = Q32[(w16 + gid + 8) * 20 + ks * 8 + tig + 4];
    }

    float oacc[4][4];
    #pragma unroll
    for (int nt = 0; nt < 4; ++nt)
        #pragma unroll
        for (int q = 0; q < 4; ++q) oacc[nt][q] = 0.f;
    float lp0 = 0.f, lp1 = 0.f;

    const uint8_t* crow0 = g_code + (size_t)(bN + r0 + w16 + gid    ) * NSEQ + tig * 2;
    const uint8_t* crow1 = g_code + (size_t)(bN + r0 + w16 + gid + 8) * NSEQ + tig * 2;

    for (int kt = 0; kt < 16; ++kt) {
        int st = kt % 3, j0 = kt * 128;

        // ---- prefetch edge codes for this tile (overlaps wait + QK MMAs) ----
        uint32_t cc[16];
        #pragma unroll
        for (int nt = 0; nt < 16; ++nt) {
            uint32_t c0 = *(const unsigned short*)(crow0 + j0 + nt * 8);
            uint32_t c1 = *(const unsigned short*)(crow1 + j0 + nt * 8);
            cc[nt] = c0 | (c1 << 16);
        }

        if (kt + 1 < 16) cp_wait<1>(); else cp_wait<0>();
        __syncthreads();
        if (kt + 2 < 16) load_kv(kt + 2, (kt + 2) % 3);

        // ---- QK^T: warp computes its 16 rows x full 128 cols ----
        const uint32_t* K32 = (const uint32_t*)(Ks0 + st * 5120);
        float sacc[16][4];
        #pragma unroll
        for (int nt = 0; nt < 16; ++nt)
            #pragma unroll
            for (int q = 0; q < 4; ++q) sacc[nt][q] = 0.f;
        #pragma unroll
        for (int ks = 0; ks < 2; ++ks) {
            #pragma unroll
            for (int nt = 0; nt < 16; ++nt) {
                int n = nt * 8 + gid;
                uint32_t b0 = K32[n * 20 + ks * 8 + tig];
                uint32_t b1 = K32[n * 20 + ks * 8 + tig + 4];
                mma16(sacc[nt], qa[ks][0], qa[ks][1], qa[ks][2], qa[ks][3], b0, b1);
            }
        }

        // ---- interleaved exp epilogue + PV MMAs ----
        const uint32_t* V32 = (const uint32_t*)(Vs0 + st * 4352);
        #pragma unroll
        for (int ks2 = 0; ks2 < 8; ++ks2) {
            uint32_t pf[4];
            #pragma unroll
            for (int half = 0; half < 2; ++half) {
                int nt = 2 * ks2 + half;
                uint32_t c = cc[nt];
                float p00 = fexp2(sacc[nt][0] + tbl2[c & 0xff]);
                float p01 = fexp2(sacc[nt][1] + tbl2[(c >> 8) & 0xff]);
                float p10 = fexp2(sacc[nt][2] + tbl2[(c >> 16) & 0xff]);
                float p11 = fexp2(sacc[nt][3] + tbl2[c >> 24]);
                lp0 += p00 + p01;
                lp1 += p10 + p11;
                __nv_bfloat162 a = __floats2bfloat162_rn(p00, p01);
                __nv_bfloat162 d = __floats2bfloat162_rn(p10, p11);
                pf[half * 2 + 0] = *(uint32_t*)&a;
                pf[half * 2 + 1] = *(uint32_t*)&d;
            }
            #pragma unroll
            for (int nt2 = 0; nt2 < 4; ++nt2) {
                int d = nt2 * 8 + gid;
                uint32_t b0 = V32[d * 68 + ks2 * 8 + tig];
                uint32_t b1 = V32[d * 68 + ks2 * 8 + tig + 4];
                mma16(oacc[nt2], pf[0], pf[1], pf[2], pf[3], b0, b1);
            }
        }
    }

    // ---- row sums: butterfly within quad (warp owns its rows) ----
    lp0 += __shfl_xor_sync(0xffffffffu, lp0, 1);
    lp0 += __shfl_xor_sync(0xffffffffu, lp0, 2);
    lp1 += __shfl_xor_sync(0xffffffffu, lp1, 1);
    lp1 += __shfl_xor_sync(0xffffffffu, lp1, 2);
    float inv0 = lp0 > 0.f ? 1.f / lp0 : 0.f;
    float inv1 = lp1 > 0.f ? 1.f / lp1 : 0.f;

    bf16* od = g_ao + ((size_t)(bN + r0)) * DIMD + h * HD;
    #pragma unroll
    for (int nt = 0; nt < 4; ++nt) {
        int d = nt * 8 + tig * 2;
        *(__nv_bfloat162*)&od[(size_t)(w16 + gid    ) * DIMD + d] =
            __floats2bfloat162_rn(oacc[nt][0] * inv0, oacc[nt][1] * inv0);
        *(__nv_bfloat162*)&od[(size_t)(w16 + gid + 8) * DIMD + d] =
            __floats2bfloat162_rn(oacc[nt][2] * inv1, oacc[nt][3] * inv1);
    }
}

// ---------------- launch ----------------
static void* sym_addr(const void* sym)
{
    void* p = nullptr;
    cudaGetSymbolAddress(&p, sym);
    return p;
}

extern "C" void kernel_launch(void* const* d_in, const int* in_sizes, int n_in,
                              void* d_out, int out_size)
{
    const float* x      = (const float*)d_in[0];
    const int*   etyp   = (const int*)  d_in[1];
    const int*   nmask  = (const int*)  d_in[2];
    const float* qkv_w  = (const float*)d_in[3];
    const float* qkv_b  = (const float*)d_in[4];
    const float* proj_w = (const float*)d_in[5];
    const float* proj_b = (const float*)d_in[6];
    const float* ebt    = (const float*)d_in[7];
    const float* ln1_g  = (const float*)d_in[8];
    const float* ln1_b  = (const float*)d_in[9];
    const float* ln2_g  = (const float*)d_in[10];
    const float* ln2_b  = (const float*)d_in[11];
    const float* ffn_w1 = (const float*)d_in[12];
    const float* ffn_b1 = (const float*)d_in[13];
    const float* ffn_w2 = (const float*)d_in[14];
    const float* ffn_b2 = (const float*)d_in[15];
    float* out = (float*)d_out;

    bf16*  ph    = (bf16*) sym_addr(g_h);
    bf16*  pao   = (bf16*) sym_addr(g_ao);
    float* px1   = (float*)sym_addr(g_x1);
    bf16*  ph2   = (bf16*) sym_addr(g_h2);
    bf16*  pmid  = (bf16*) sym_addr(g_mid);
    bf16*  pwqkv = (bf16*) sym_addr(g_wqkv);
    bf16*  pwproj= (bf16*) sym_addr(g_wproj);
    bf16*  pwf1  = (bf16*) sym_addr(g_wf1);
    bf16*  pwf2  = (bf16*) sym_addr(g_wf2);
    uint8_t* pcode = (uint8_t*)sym_addr(g_code);

    const int ATTN_SMEM = (5120 + 3 * 5120 + 3 * 4352) * 2 + 64;  // 67136
    const int GSM_64_128 = 3 * (64 * 40 + 128 * 40) * 2;          // 46080
    const int GSM_64_64  = 3 * (64 * 40 + 64 * 40) * 2;           // 30720
    cudaFuncSetAttribute(attn_mma, cudaFuncAttributeMaxDynamicSharedMemorySize, ATTN_SMEM);
    cudaFuncSetAttribute(mma_gemm<64,128,DIMD,3*DIMD,0>, cudaFuncAttributeMaxDynamicSharedMemorySize, GSM_64_128);
    cudaFuncSetAttribute(mma_gemm<64,64,DIMD,DIMD,1>,    cudaFuncAttributeMaxDynamicSharedMemorySize, GSM_64_64);
    cudaFuncSetAttribute(mma_gemm<64,128,DIMD,FFD,2>,    cudaFuncAttributeMaxDynamicSharedMemorySize, GSM_64_128);
    cudaFuncSetAttribute(mma_gemm<64,64,FFD,DIMD,3>,     cudaFuncAttributeMaxDynamicSharedMemorySize, GSM_64_64);

    // 0) fused weight conversion + edge code precompute
    wconv_all<<<768, 256>>>(qkv_w, proj_w, ffn_w1, ffn_w2);
    edge_code_kernel<<<dim3(NSEQ, BNUM), 256>>>(etyp, nmask, pcode);

    // 1) LN1 -> bf16
    ln_kernel<<<ROWS, 256>>>(x, ln1_g, ln1_b, ph);
    // 2) QKV GEMM + scatter (q scaled; k normal; v transposed)
    mma_gemm<64, 128, DIMD, 3*DIMD, 0><<<dim3(6, 64), 256, GSM_64_128>>>(
        ph, pwqkv, qkv_b, nullptr, nullptr, nullptr, nullptr);
    // 3) attention
    attn_mma<<<BNUM * NHEAD * (NSEQ / 128), 256, ATTN_SMEM>>>(ebt);
    // 4) proj + residual + node mask -> x1 (fp32)
    mma_gemm<64, 64, DIMD, DIMD, 1><<<dim3(4, 64), 256, GSM_64_64>>>(
        pao, pwproj, proj_b, x, nmask, px1, nullptr);
    // 5) LN2 -> bf16
    ln_kernel<<<ROWS, 256>>>(px1, ln2_g, ln2_b, ph2);
    // 6) FFN1 + exact GELU -> bf16 mid
    mma_gemm<64, 128, DIMD, FFD, 2><<<dim3(8, 64), 256, GSM_64_128>>>(
        ph2, pwf1, ffn_b1, nullptr, nullptr, nullptr, pmid);
    // 7) FFN2 + node mask + residual -> out (fp32)
    mma_gemm<64, 64, FFD, DIMD, 3><<<dim3(4, 64), 256, GSM_64_64>>>(
        pmid, pwf2, ffn_b2, px1, nmask, out, nullptr);
}

// round 8
// speedup vs baseline: 1.0893x; 1.0179x over previous
#include <cuda_runtime.h>
#include <cuda_bf16.h>
#include <cuda_fp16.h>
#include <math.h>
#include <stdint.h>

#define BNUM 2
#define NSEQ 2048
#define DIMD 256
#define NHEAD 8
#define HD 32
#define FFD 1024
#define ROWS (BNUM*NSEQ)   // 4096

typedef __nv_bfloat16 bf16;

#define QSCALE (0.17677669529663687f * 1.4426950408889634f)
#define LOG2E  1.4426950408889634f

// ---------------- scratch (device globals, no allocation) ----------------
__device__ bf16  g_h  [ROWS*DIMD];
__device__ bf16  g_q  [BNUM*NHEAD*NSEQ*HD];
__device__ bf16  g_k  [BNUM*NHEAD*NSEQ*HD];
__device__ half  g_vT [BNUM*NHEAD*HD*NSEQ];   // [b][h][d][n], f16 for PV f16 MMA
__device__ bf16  g_ao [ROWS*DIMD];
__device__ float g_x1 [ROWS*DIMD];
__device__ bf16  g_h2 [ROWS*DIMD];
__device__ bf16  g_mid[ROWS*FFD];
__device__ uint8_t g_code[(size_t)BNUM*NSEQ*NSEQ];   // 0 = masked, else edge_type+1
__device__ bf16  g_wqkv [3*DIMD*DIMD];
__device__ bf16  g_wproj[DIMD*DIMD];
__device__ bf16  g_wf1  [FFD*DIMD];
__device__ bf16  g_wf2  [DIMD*FFD];

// ---------------- helpers ----------------
__device__ __forceinline__ void cpasync16(void* sdst, const void* gsrc){
    unsigned s = (unsigned)__cvta_generic_to_shared(sdst);
    asm volatile("cp.async.cg.shared.global [%0], [%1], 16;" :: "r"(s), "l"(gsrc));
}
#define CP_COMMIT() asm volatile("cp.async.commit_group;")
template<int N> __device__ __forceinline__ void cp_wait(){
    asm volatile("cp.async.wait_group %0;" :: "n"(N));
}

__device__ __forceinline__ void mma16(float* c,
    uint32_t a0, uint32_t a1, uint32_t a2, uint32_t a3,
    uint32_t b0, uint32_t b1)
{
    asm volatile("mma.sync.aligned.m16n8k16.row.col.f32.bf16.bf16.f32 "
        "{%0,%1,%2,%3}, {%4,%5,%6,%7}, {%8,%9}, {%0,%1,%2,%3};"
        : "+f"(c[0]), "+f"(c[1]), "+f"(c[2]), "+f"(c[3])
        : "r"(a0), "r"(a1), "r"(a2), "r"(a3), "r"(b0), "r"(b1));
}
__device__ __forceinline__ void mma16h(float* c,
    uint32_t a0, uint32_t a1, uint32_t a2, uint32_t a3,
    uint32_t b0, uint32_t b1)
{
    asm volatile("mma.sync.aligned.m16n8k16.row.col.f32.f16.f16.f32 "
        "{%0,%1,%2,%3}, {%4,%5,%6,%7}, {%8,%9}, {%0,%1,%2,%3};"
        : "+f"(c[0]), "+f"(c[1]), "+f"(c[2]), "+f"(c[3])
        : "r"(a0), "r"(a1), "r"(a2), "r"(a3), "r"(b0), "r"(b1));
}
__device__ __forceinline__ uint32_t hex2(uint32_t x){
    uint32_t y; asm("ex2.approx.f16x2 %0, %1;" : "=r"(y) : "r"(x)); return y;
}

// ---------------- LN body (shared by setup + LN2) ----------------
__device__ __forceinline__ void ln_body(const float* __restrict__ x,
                                        const float* __restrict__ g,
                                        const float* __restrict__ b,
                                        bf16* __restrict__ y, int row,
                                        float* red, float* stat)
{
    int t = threadIdx.x;
    float v = x[(size_t)row * DIMD + t];
    float s = v;
    #pragma unroll
    for (int o = 16; o > 0; o >>= 1) s += __shfl_xor_sync(0xffffffffu, s, o);
    if ((t & 31) == 0) red[t >> 5] = s;
    __syncthreads();
    if (t < 32) {
        float r = (t < 8) ? red[t] : 0.f;
        #pragma unroll
        for (int o = 4; o > 0; o >>= 1) r += __shfl_xor_sync(0xffffffffu, r, o);
        if (t == 0) stat[0] = r * (1.0f / DIMD);
    }
    __syncthreads();
    float mu = stat[0];
    float d  = v - mu;
    float s2 = d * d;
    #pragma unroll
    for (int o = 16; o > 0; o >>= 1) s2 += __shfl_xor_sync(0xffffffffu, s2, o);
    if ((t & 31) == 0) red[t >> 5] = s2;
    __syncthreads();
    if (t < 32) {
        float r = (t < 8) ? red[t] : 0.f;
        #pragma unroll
        for (int o = 4; o > 0; o >>= 1) r += __shfl_xor_sync(0xffffffffu, r, o);
        if (t == 0) stat[1] = rsqrtf(r * (1.0f / DIMD) + 1e-5f);
    }
    __syncthreads();
    y[(size_t)row * DIMD + t] = __float2bfloat16(d * stat[1] * g[t] + b[t]);
}

// ---------------- fused setup: wconv + edge code + LN1 (independent) --------
__global__ void __launch_bounds__(256)
setup_kernel(const float* __restrict__ w_qkv, const float* __restrict__ w_proj,
             const float* __restrict__ w_f1,  const float* __restrict__ w_f2,
             const int* __restrict__ et, const int* __restrict__ nm,
             const float* __restrict__ x, const float* __restrict__ ln1_g,
             const float* __restrict__ ln1_b)
{
    __shared__ float tile[32][33];
    __shared__ float red[8];
    __shared__ float stat[2];
    int id = blockIdx.x;

    if (id < 768) {
        // ---- weight transpose+convert: W[k][n] fp32 -> Wt[n][k] bf16 ----
        const float* W; bf16* Wt; int K, N; bool qs = false;
        if (id < 192)      { W = w_qkv;  Wt = g_wqkv;  K = 256;  N = 768;  qs = true; }
        else if (id < 256) { id -= 192; W = w_proj; Wt = g_wproj; K = 256;  N = 256; }
        else if (id < 512) { id -= 256; W = w_f1;   Wt = g_wf1;   K = 256;  N = 1024; }
        else               { id -= 512; W = w_f2;   Wt = g_wf2;   K = 1024; N = 256; }
        int tn = id % (N / 32), tk = id / (N / 32);
        int tx = threadIdx.x & 31, ty = threadIdx.x >> 5;
        #pragma unroll
        for (int r = 0; r < 4; ++r)
            tile[ty + r * 8][tx] = W[(size_t)(tk * 32 + ty + r * 8) * N + tn * 32 + tx];
        __syncthreads();
        float mul = (qs && tn < 8) ? QSCALE : 1.f;
        #pragma unroll
        for (int r = 0; r < 4; ++r) {
            int n = tn * 32 + ty + r * 8;
            Wt[(size_t)n * K + tk * 32 + tx] = __float2bfloat16(tile[tx][ty + r * 8] * mul);
        }
    } else if (id < 768 + 4096) {
        // ---- edge code ----
        int idx = id - 768;
        int i = idx & 2047, b = idx >> 11;
        int bN = b * NSEQ;
        int nmi = nm[bN + i];
        const int* er = et + (size_t)(bN + i) * NSEQ;
        uint8_t* cr = g_code + (size_t)(bN + i) * NSEQ;
        for (int j = threadIdx.x * 4; j < NSEQ; j += 1024) {
            int4 e = *(const int4*)(er + j);
            int4 m = *(const int4*)(nm + bN + j);
            uchar4 c;
            c.x = (nmi && m.x && (e.x != 0 || i == j    )) ? (uint8_t)(e.x + 1) : 0;
            c.y = (nmi && m.y && (e.y != 0 || i == j + 1)) ? (uint8_t)(e.y + 1) : 0;
            c.z = (nmi && m.z && (e.z != 0 || i == j + 2)) ? (uint8_t)(e.z + 2 - 2) : 0;
            c.w = (nmi && m.w && (e.w != 0 || i == j + 3)) ? (uint8_t)(e.w + 1) : 0;
            c.z = (nmi && m.z && (e.z != 0 || i == j + 2)) ? (uint8_t)(e.z + 1) : 0;
            *(uchar4*)(cr + j) = c;
        }
    } else {
        // ---- LN1 ----
        ln_body(x, ln1_g, ln1_b, g_h, id - (768 + 4096), red, stat);
    }
}

// ---------------- standalone LN (for LN2) ----------------
__global__ void ln_kernel(const float* __restrict__ x,
                          const float* __restrict__ g,
                          const float* __restrict__ b,
                          bf16* __restrict__ y)
{
    __shared__ float red[8];
    __shared__ float stat[2];
    ln_body(x, g, b, y, blockIdx.x, red, stat);
}

// ---------------- bf16 MMA GEMM, 3-stage cp.async pipeline ----------------
template<int BM, int BN, int KD, int NT, int MODE>
__global__ void __launch_bounds__(256, 2)
mma_gemm(const bf16* __restrict__ A, const bf16* __restrict__ Wt,
         const float* __restrict__ bias, const float* __restrict__ extra,
         const int* __restrict__ nm, float* __restrict__ outf, bf16* __restrict__ outb)
{
    constexpr int WM  = BM / 32;
    constexpr int WN  = 8 / WM;
    constexpr int WTN = BN / WN;
    constexpr int NTN = WTN / 8;
    constexpr int CA  = (BM * 32 / 8) / 256;
    constexpr int CB  = (BN * 32 / 8) / 256;
    constexpr int NK  = KD / 32;

    extern __shared__ __align__(16) bf16 gsm[];
    bf16* As = gsm;                 // [3][BM*40]
    bf16* Bs = gsm + 3 * BM * 40;   // [3][BN*40]

    int t = threadIdx.x, lane = t & 31, warp = t >> 5;
    int gid = lane >> 2, tig = lane & 3;
    int wm = warp % WM, wn = warp / WM;
    int rm = blockIdx.y * BM, cn = blockIdx.x * BN;
    const bf16* Ag = A  + (size_t)rm * KD;
    const bf16* Bg = Wt + (size_t)cn * KD;

    float acc[2][NTN][4];
    #pragma unroll
    for (int mi = 0; mi < 2; ++mi)
        #pragma unroll
        for (int nt = 0; nt < NTN; ++nt)
            #pragma unroll
            for (int q = 0; q < 4; ++q) acc[mi][nt][q] = 0.f;

    auto load_stage = [&](int k0, int st) {
        bf16* Asd = As + st * BM * 40;
        bf16* Bsd = Bs + st * BN * 40;
        #pragma unroll
        for (int i = 0; i < CA; ++i) {
            int c = t + i * 256, row = c >> 2, off = (c & 3) * 8;
            cpasync16(&Asd[row * 40 + off], Ag + (size_t)row * KD + k0 + off);
        }
        #pragma unroll
        for (int i = 0; i < CB; ++i) {
            int c = t + i * 256, row = c >> 2, off = (c & 3) * 8;
            cpasync16(&Bsd[row * 40 + off], Bg + (size_t)row * KD + k0 + off);
        }
        CP_COMMIT();
    };

    load_stage(0, 0);
    load_stage(32, 1);
    for (int i = 0; i < NK; ++i) {
        int st = i % 3;
        if (i + 1 < NK) cp_wait<1>(); else cp_wait<0>();
        __syncthreads();
        if (i + 2 < NK) load_stage((i + 2) * 32, (i + 2) % 3);

        const uint32_t* A32 = (const uint32_t*)(As + st * BM * 40);
        const uint32_t* B32 = (const uint32_t*)(Bs + st * BN * 40);
        #pragma unroll
        for (int ks = 0; ks < 2; ++ks) {
            uint32_t af[2][4];
            #pragma unroll
            for (int mi = 0; mi < 2; ++mi) {
                int base = wm * 32 + mi * 16;
                af[mi][0] = A32[(base + gid    ) * 20 + ks * 8 + tig    ];
                af[mi][1] = A32[(base + gid + 8) * 20 + ks * 8 + tig    ];
                af[mi][2] = A32[(base + gid    ) * 20 + ks * 8 + tig + 4];
                af[mi][3] = A32[(base + gid + 8) * 20 + ks * 8 + tig + 4];
            }
            #pragma unroll
            for (int nt = 0; nt < NTN; ++nt) {
                int n = wn * WTN + nt * 8 + gid;
                uint32_t b0 = B32[n * 20 + ks * 8 + tig];
                uint32_t b1 = B32[n * 20 + ks * 8 + tig + 4];
                mma16(acc[0][nt], af[0][0], af[0][1], af[0][2], af[0][3], b0, b1);
                mma16(acc[1][nt], af[1][0], af[1][1], af[1][2], af[1][3], b0, b1);
            }
        }
    }
    __syncthreads();

    // ---- epilogue ----
    #pragma unroll
    for (int mi = 0; mi < 2; ++mi) {
        #pragma unroll
        for (int half_i = 0; half_i < 2; ++half_i) {
            int r = rm + wm * 32 + mi * 16 + gid + half_i * 8;
            float mrow = 0.f;
            if (MODE == 1 || MODE == 3) mrow = nm[r] ? 1.f : 0.f;
            #pragma unroll
            for (int nt = 0; nt < NTN; ++nt) {
                int c = cn + wn * WTN + nt * 8 + tig * 2;
                float bmul = (MODE == 0 && c < DIMD) ? QSCALE : 1.f;
                float v0 = acc[mi][nt][half_i * 2 + 0] + bias[c] * bmul;
                float v1 = acc[mi][nt][half_i * 2 + 1] + bias[c + 1] * bmul;
                if (MODE == 0) {
                    int part = c >> 8, hh = (c >> 5) & 7, dd = c & 31;
                    int b2 = r >> 11, n = r & 2047;
                    if (part == 2) {
                        size_t base = ((size_t)(b2 * NHEAD + hh) * HD + dd) * NSEQ + n;
                        g_vT[base]        = __float2half_rn(v0);
                        g_vT[base + NSEQ] = __float2half_rn(v1);
                    } else {
                        bf16* dst = (part == 0) ? g_q : g_k;
                        __nv_bfloat162 pv = __floats2bfloat162_rn(v0, v1);
                        *(__nv_bfloat162*)&dst[((size_t)(b2 * NHEAD + hh) * NSEQ + n) * HD + dd] = pv;
                    }
                } else if (MODE == 2) {
                    float g0 = 0.5f * v0 * (1.f + erff(v0 * 0.70710678118654752f));
                    float g1 = 0.5f * v1 * (1.f + erff(v1 * 0.70710678118654752f));
                    *(__nv_bfloat162*)&outb[(size_t)r * NT + c] = __floats2bfloat162_rn(g0, g1);
                } else {
                    float2 ex = *(const float2*)&extra[(size_t)r * NT + c];
                    *(float2*)&outf[(size_t)r * NT + c] =
                        make_float2(ex.x + v0 * mrow, ex.y + v1 * mrow);
                }
            }
        }
    }
}

// ---------------- bf16/f16 MMA flash attention ----------------
// QK in bf16; exp via ex2.approx.f16x2; PV in f16 with ones-column row sums.
__global__ void __launch_bounds__(256, 2)
attn_mma(const float* __restrict__ ebt)
{
    extern __shared__ __align__(16) bf16 smb[];
    bf16* Qs  = smb;                        // 128*40
    bf16* Ks0 = Qs + 5120;                  // 3 stages x 128*40
    half* Vs0 = (half*)(Ks0 + 3 * 5120);    // 3 stages x 40*136 (rows 32..39 const)
    float* tbl2 = (float*)(Vs0 + 3 * 5440); // 16

    int tid = threadIdx.x, lane = tid & 31, warp = tid >> 5;
    int gid = lane >> 2, tig = lane & 3;
    int bid = blockIdx.x;
    int h = bid & 7, rb = (bid >> 3) & 15, b = bid >> 7;  // h fastest: code L2 reuse
    int r0 = rb * 128;
    const int bN = b * NSEQ;
    int w16 = warp * 16;

    const bf16* qptr = g_q  + ((size_t)(b * NHEAD + h) * NSEQ + r0) * HD;
    const bf16* kbh  = g_k  + (size_t)(b * NHEAD + h) * NSEQ * HD;
    const half* vT   = g_vT + (size_t)(b * NHEAD + h) * HD * NSEQ;

    auto load_kv = [&](int kt, int st) {
        int j0 = kt * 128;
        bf16* Ksd = Ks0 + st * 5120;
        half* Vsd = Vs0 + st * 5440;
        #pragma unroll
        for (int i = 0; i < 2; ++i) {
            int c = tid + i * 256, row = c >> 2, off = (c & 3) * 8;
            cpasync16(&Ksd[row * 40 + off], kbh + (size_t)(j0 + row) * HD + off);
        }
        #pragma unroll
        for (int i = 0; i < 2; ++i) {
            int c = tid + i * 256, d = c >> 4, off = (c & 15) * 8;
            cpasync16(&Vsd[d * 136 + off], vT + (size_t)d * NSEQ + j0 + off);
        }
        CP_COMMIT();
    };

    load_kv(0, 0);
    load_kv(1, 1);

    #pragma unroll
    for (int i = 0; i < 2; ++i) {
        int c = tid + i * 256, row = c >> 2, off = (c & 3) * 8;
        *(uint4*)&Qs[row * 40 + off] = *(const uint4*)(qptr + (size_t)row * HD + off);
    }
    // constant V rows 32..39 for all 3 stages: row 32 = 1.0 (row sums), rest 0
    for (int u = tid; u < 3 * 8 * 64; u += 256) {
        int stg = u / 512, rem = u % 512, rowe = rem / 64, col = rem % 64;
        uint32_t val = (rowe == 0) ? 0x3C003C00u : 0u;   // half2(1,1) / half2(0,0)
        *(uint32_t*)&Vs0[stg * 5440 + (32 + rowe) * 136 + col * 2] = val;
    }
    if (tid < 16)
        tbl2[tid] = (tid == 0) ? -30000.f
                  : (tid < 10 ? ebt[(tid - 1) * NHEAD + h] * LOG2E : 0.f);
    __syncthreads();

    // Q fragments for this warp's 16 rows
    const uint32_t* Q32 = (const uint32_t*)Qs;
    uint32_t qa[2][4];
    #pragma unroll
    for (int ks = 0; ks < 2; ++ks) {
        qa[ks][0] = Q32[(w16 + gid    ) * 20 + ks * 8 + tig    ];
        qa[ks][1] = Q32[(w16 + gid + 8) * 20 + ks * 8 + tig    ];
        qa[ks][2] = Q32[(w16 + gid    ) * 20 + ks * 8 + tig + 4];
        qa[ks][3] = Q32[(w16 + gid + 8) * 20 + ks * 8 + tig + 4];
    }

    float oacc[5][4];   // [4] = ones-column (row sums)
    #pragma unroll
    for (int nt = 0; nt < 5; ++nt)
        #pragma unroll
        for (int q = 0; q < 4; ++q) oacc[nt][q] = 0.f;

    const uint8_t* crow0 = g_code + (size_t)(bN + r0 + w16 + gid    ) * NSEQ + tig * 2;
    const uint8_t* crow1 = g_code + (size_t)(bN + r0 + w16 + gid + 8) * NSEQ + tig * 2;

    for (int kt = 0; kt < 16; ++kt) {
        int st = kt % 3, j0 = kt * 128;

        // ---- prefetch edge codes for this tile (overlaps wait + QK MMAs) ----
        uint32_t cc[16];
        #pragma unroll
        for (int nt = 0; nt < 16; ++nt) {
            uint32_t c0 = *(const unsigned short*)(crow0 + j0 + nt * 8);
            uint32_t c1 = *(const unsigned short*)(crow1 + j0 + nt * 8);
            cc[nt] = c0 | (c1 << 16);
        }

        if (kt + 1 < 16) cp_wait<1>(); else cp_wait<0>();
        __syncthreads();
        if (kt + 2 < 16) load_kv(kt + 2, (kt + 2) % 3);

        // ---- QK^T: warp computes its 16 rows x full 128 cols ----
        const uint32_t* K32 = (const uint32_t*)(Ks0 + st * 5120);
        float sacc[16][4];
        #pragma unroll
        for (int nt = 0; nt < 16; ++nt)
            #pragma unroll
            for (int q = 0; q < 4; ++q) sacc[nt][q] = 0.f;
        #pragma unroll
        for (int ks = 0; ks < 2; ++ks) {
            #pragma unroll
            for (int nt = 0; nt < 16; ++nt) {
                int n = nt * 8 + gid;
                uint32_t b0 = K32[n * 20 + ks * 8 + tig];
                uint32_t b1 = K32[n * 20 + ks * 8 + tig + 4];
                mma16(sacc[nt], qa[ks][0], qa[ks][1], qa[ks][2], qa[ks][3], b0, b1);
            }
        }

        // ---- interleaved f16x2 exp epilogue + f16 PV MMAs ----
        const uint32_t* V32 = (const uint32_t*)(Vs0 + st * 5440);
        #pragma unroll
        for (int ks2 = 0; ks2 < 8; ++ks2) {
            uint32_t pf[4];
            #pragma unroll
            for (int half_i = 0; half_i < 2; ++half_i) {
                int nt = 2 * ks2 + half_i;
                uint32_t c = cc[nt];
                __half2 a01 = __floats2half2_rn(sacc[nt][0] + tbl2[c & 0xff],
                                                sacc[nt][1] + tbl2[(c >> 8) & 0xff]);
                __half2 a23 = __floats2half2_rn(sacc[nt][2] + tbl2[(c >> 16) & 0xff],
                                                sacc[nt][3] + tbl2[c >> 24]);
                pf[half_i * 2 + 0] = hex2(*(uint32_t*)&a01);
                pf[half_i * 2 + 1] = hex2(*(uint32_t*)&a23);
            }
            #pragma unroll
            for (int nt2 = 0; nt2 < 5; ++nt2) {
                int d = nt2 * 8 + gid;
                uint32_t b0 = V32[d * 68 + ks2 * 8 + tig];
                uint32_t b1 = V32[d * 68 + ks2 * 8 + tig + 4];
                mma16h(oacc[nt2], pf[0], pf[1], pf[2], pf[3], b0, b1);
            }
        }
    }

    // ---- row sums live in oacc[4] col 32 (tig==0 lanes); broadcast in quad ----
    float lp0 = __shfl_sync(0xffffffffu, oacc[4][0], lane & ~3);
    float lp1 = __shfl_sync(0xffffffffu, oacc[4][2], lane & ~3);
    float inv0 = lp0 > 0.f ? 1.f / lp0 : 0.f;
    float inv1 = lp1 > 0.f ? 1.f / lp1 : 0.f;

    bf16* od = g_ao + ((size_t)(bN + r0)) * DIMD + h * HD;
    #pragma unroll
    for (int nt = 0; nt < 4; ++nt) {
        int d = nt * 8 + tig * 2;
        *(__nv_bfloat162*)&od[(size_t)(w16 + gid    ) * DIMD + d] =
            __floats2bfloat162_rn(oacc[nt][0] * inv0, oacc[nt][1] * inv0);
        *(__nv_bfloat162*)&od[(size_t)(w16 + gid + 8) * DIMD + d] =
            __floats2bfloat162_rn(oacc[nt][2] * inv1, oacc[nt][3] * inv1);
    }
}

// ---------------- launch ----------------
static void* sym_addr(const void* sym)
{
    void* p = nullptr;
    cudaGetSymbolAddress(&p, sym);
    return p;
}

extern "C" void kernel_launch(void* const* d_in, const int* in_sizes, int n_in,
                              void* d_out, int out_size)
{
    const float* x      = (const float*)d_in[0];
    const int*   etyp   = (const int*)  d_in[1];
    const int*   nmask  = (const int*)  d_in[2];
    const float* qkv_w  = (const float*)d_in[3];
    const float* qkv_b  = (const float*)d_in[4];
    const float* proj_w = (const float*)d_in[5];
    const float* proj_b = (const float*)d_in[6];
    const float* ebt    = (const float*)d_in[7];
    const float* ln1_g  = (const float*)d_in[8];
    const float* ln1_b  = (const float*)d_in[9];
    const float* ln2_g  = (const float*)d_in[10];
    const float* ln2_b  = (const float*)d_in[11];
    const float* ffn_w1 = (const float*)d_in[12];
    const float* ffn_b1 = (const float*)d_in[13];
    const float* ffn_w2 = (const float*)d_in[14];
    const float* ffn_b2 = (const float*)d_in[15];
    float* out = (float*)d_out;

    bf16*  ph    = (bf16*) sym_addr(g_h);
    bf16*  pao   = (bf16*) sym_addr(g_ao);
    float* px1   = (float*)sym_addr(g_x1);
    bf16*  ph2   = (bf16*) sym_addr(g_h2);
    bf16*  pmid  = (bf16*) sym_addr(g_mid);
    bf16*  pwqkv = (bf16*) sym_addr(g_wqkv);
    bf16*  pwproj= (bf16*) sym_addr(g_wproj);
    bf16*  pwf1  = (bf16*) sym_addr(g_wf1);
    bf16*  pwf2  = (bf16*) sym_addr(g_wf2);

    const int ATTN_SMEM = (5120 + 3 * 5120) * 2 + 3 * 5440 * 2 + 64;  // 73664
    const int GSM_64_128 = 3 * (64 * 40 + 128 * 40) * 2;              // 46080
    const int GSM_64_64  = 3 * (64 * 40 + 64 * 40) * 2;               // 30720
    cudaFuncSetAttribute(attn_mma, cudaFuncAttributeMaxDynamicSharedMemorySize, ATTN_SMEM);
    cudaFuncSetAttribute(mma_gemm<64,128,DIMD,3*DIMD,0>, cudaFuncAttributeMaxDynamicSharedMemorySize, GSM_64_128);
    cudaFuncSetAttribute(mma_gemm<64,64,DIMD,DIMD,1>,    cudaFuncAttributeMaxDynamicSharedMemorySize, GSM_64_64);
    cudaFuncSetAttribute(mma_gemm<64,128,DIMD,FFD,2>,    cudaFuncAttributeMaxDynamicSharedMemorySize, GSM_64_128);
    cudaFuncSetAttribute(mma_gemm<64,64,FFD,DIMD,3>,     cudaFuncAttributeMaxDynamicSharedMemorySize, GSM_64_64);

    // 0+1) fused setup: weight convert + edge code + LN1 (all independent)
    setup_kernel<<<768 + 4096 + ROWS, 256>>>(qkv_w, proj_w, ffn_w1, ffn_w2,
                                             etyp, nmask, x, ln1_g, ln1_b);
    // 2) QKV GEMM + scatter (q scaled; k normal bf16; v transposed f16)
    mma_gemm<64, 128, DIMD, 3*DIMD, 0><<<dim3(6, 64), 256, GSM_64_128>>>(
        ph, pwqkv, qkv_b, nullptr, nullptr, nullptr, nullptr);
    // 3) attention
    attn_mma<<<BNUM * NHEAD * (NSEQ / 128), 256, ATTN_SMEM>>>(ebt);
    // 4) proj + residual + node mask -> x1 (fp32)
    mma_gemm<64, 64, DIMD, DIMD, 1><<<dim3(4, 64), 256, GSM_64_64>>>(
        pao, pwproj, proj_b, x, nmask, px1, nullptr);
    // 5) LN2 -> bf16
    ln_kernel<<<ROWS, 256>>>(px1, ln2_g, ln2_b, ph2);
    // 6) FFN1 + exact GELU -> bf16 mid
    mma_gemm<64, 128, DIMD, FFD, 2><<<dim3(8, 64), 256, GSM_64_128>>>(
        ph2, pwf1, ffn_b1, nullptr, nullptr, nullptr, pmid);
    // 7) FFN2 + node mask + residual -> out (fp32)
    mma_gemm<64, 64, FFD, DIMD, 3><<<dim3(4, 64), 256, GSM_64_64>>>(
        pmid, pwf2, ffn_b2, px1, nmask, out, nullptr);
}